// round 12
// baseline (speedup 1.0000x reference)
#include <cuda_runtime.h>

#define N_NODES 30000
#define N_EDGES 480000

// ---------------------------------------------------------------------------
// Scratch (static device globals — no allocation)
// y layout per node: [l-block][m][ch(8)] -> l=0 @0, l=1 @8, l=2 @32. 72 f/node.
// ---------------------------------------------------------------------------
__device__ __align__(16) float g_ybuf[N_NODES * 72];

// Compacted CG (selection rule m = (p-l1)+(q-l2)+lo):
// g_cg2[combo*25 + p*5 + q] = C[m(p,q), p, q]  (0 if out of range)
__device__ float g_cg2[27 * 25];

// Orientation-optimized fused weights, layout per path [d*CA + c] (c = A-side
// channel, fastest). Regions: yy 11 paths (o-stride 704) @0; yx 15 paths
// (o-stride 480) @5632; xx 11 paths (o-stride 176) @9472.
__device__ __align__(16) float g_wt[10880];

// ---------------------------------------------------------------------------
// Kernel 1: zero y accumulator
// ---------------------------------------------------------------------------
__global__ void zero_kernel() {
    int i = blockIdx.x * blockDim.x + threadIdx.x;
    if (i < N_NODES * 18) {
        ((float4*)g_ybuf)[i] = make_float4(0.f, 0.f, 0.f, 0.f);
    }
}

// ---------------------------------------------------------------------------
// Kernel 2: Clebsch-Gordan coefficients (deterministic, tiny)
// ---------------------------------------------------------------------------
__device__ double dfac(int n) {
    double r = 1.0;
    for (int i = 2; i <= n; i++) r *= (double)i;
    return r;
}

__device__ double cg_coeff(int j1, int m1, int j2, int m2, int j, int m) {
    if (m != m1 + m2) return 0.0;
    int dj = j1 - j2; if (dj < 0) dj = -dj;
    if (j < dj || j > j1 + j2) return 0.0;
    double pre = sqrt((2.0 * j + 1.0) * dfac(j + j1 - j2) * dfac(j - j1 + j2) *
                      dfac(j1 + j2 - j) / dfac(j1 + j2 + j + 1));
    pre *= sqrt(dfac(j + m) * dfac(j - m) * dfac(j1 - m1) * dfac(j1 + m1) *
                dfac(j2 - m2) * dfac(j2 + m2));
    double s = 0.0;
    for (int k = 0; k <= j1 + j2 - j; k++) {
        int d0 = k;
        int d1 = j1 + j2 - j - k;
        int d2 = j1 - m1 - k;
        int d3 = j2 + m2 - k;
        int d4 = j - j2 + m1 + k;
        int d5 = j - j1 - m2 + k;
        if (d0 < 0 || d1 < 0 || d2 < 0 || d3 < 0 || d4 < 0 || d5 < 0) continue;
        double den = dfac(d0) * dfac(d1) * dfac(d2) * dfac(d3) * dfac(d4) * dfac(d5);
        s += ((k & 1) ? -1.0 : 1.0) / den;
    }
    return pre * s;
}

__global__ void cg_init_kernel() {
    int combo = blockIdx.x;           // 0..26
    int l1 = combo / 9;
    int l2 = (combo / 3) % 3;
    int lo = combo % 3;
    int t = threadIdx.x;              // 0..24
    int p = t / 5, q = t % 5;
    int m = (p - l1) + (q - l2) + lo; // selection rule
    float val = 0.f;
    if (p <= 2 * l1 && q <= 2 * l2 && m >= 0 && m <= 2 * lo) {
        val = (float)cg_coeff(l1, p - l1, l2, q - l2, lo, m - lo);
    }
    g_cg2[combo * 25 + t] = val;
}

// ---------------------------------------------------------------------------
// Kernel 2b: fused + orientation-optimized weight table (as round 9)
// ---------------------------------------------------------------------------
__global__ void wt_init_kernel(const float* __restrict__ wyy0, const float* __restrict__ wyy1,
                               const float* __restrict__ wyy2, const float* __restrict__ wyx0,
                               const float* __restrict__ wyx1, const float* __restrict__ wyx2,
                               const float* __restrict__ wxx0, const float* __restrict__ wxx1,
                               const float* __restrict__ wxx2) {
    int t = blockIdx.x * blockDim.x + threadIdx.x;
    if (t >= 10880) return;

    const int  loF[11]  = {0, 0, 0, 1, 1, 1, 1, 2, 2, 2, 2};
    const int  kaF[11]  = {0, 1, 2, 1, 2, 4, 5, 3, 1, 4, 5};
    const int  kbF[11]  = {-1, -1, -1, 0, -1, 3, -1, 0, -1, 2, -1};
    const float sgF[11] = {0.f, 0.f, 0.f, 1.f, 0.f, 1.f, 0.f, 1.f, 0.f, -1.f, 0.f};

    float val;
    if (t < 5632) {                       // yy fused, CA=CB=8
        int o = t / 704, v = t % 704;
        int pk = v / 64, w = v % 64, d = w / 8, c = w % 8;
        const float* S[3] = {wyy0, wyy1, wyy2};
        const float* src = S[loF[pk]];
        val = src[(kaF[pk] * 64 + c * 8 + d) * 8 + o];
        if (kbF[pk] >= 0)
            val += sgF[pk] * src[(kbF[pk] * 64 + d * 8 + c) * 8 + o];
    } else if (t < 9472) {                // yx, 15 paths, per-path orientation
        int u = t - 5632;
        int o = u / 480, v = u % 480;
        int pk = v / 32, w = v % 32;
        const int  loX[15]  = {0,0,0, 1,1,1,1,1,1, 2,2,2,2,2,2};
        const int  kX[15]   = {0,1,2, 0,1,2,3,4,5, 0,1,2,3,4,5};
        const int  axF[15]  = {1,1,1, 1,0,1,1,0,1, 1,1,1,0,0,1};
        const float sgX[15] = {1.f,1.f,1.f, 1.f,0.f,-1.f,1.f,0.f,-1.f,
                               1.f,1.f,-1.f,0.f,0.f,1.f};
        const float* S[3] = {wyx0, wyx1, wyx2};
        const float* src = S[loX[pk]];
        if (axF[pk]) {                    // A=x: same linear index, sign-scaled
            val = sgX[pk] * src[(kX[pk] * 32 + w) * 8 + o];
        } else {                          // A=y: transpose c,d
            int d = w / 8, c = w % 8;
            val = src[(kX[pk] * 32 + c * 4 + d) * 8 + o];
        }
    } else {                              // xx fused, CA=CB=4
        int u = t - 9472;
        int o = u / 176, v = u % 176;
        int pk = v / 16, w = v % 16, d = w / 4, c = w % 4;
        const float* S[3] = {wxx0, wxx1, wxx2};
        const float* src = S[loF[pk]];
        val = src[(kaF[pk] * 16 + c * 4 + d) * 8 + o];
        if (kbF[pk] >= 0)
            val += sgF[pk] * src[(kbF[pk] * 16 + d * 4 + c) * 8 + o];
    }
    g_wt[t] = val;
}

// ---------------------------------------------------------------------------
// Path variants
// ---------------------------------------------------------------------------

template <int L1, int L2, int LO>
__device__ __forceinline__ void path_rr(float* __restrict__ acc,
                                        const float (&A)[8 * (2 * L1 + 1)],
                                        const float (&B)[8 * (2 * L2 + 1)],
                                        const float* __restrict__ Wt,
                                        const float* __restrict__ sCG) {
    constexpr int P = 2 * L1 + 1, Q = 2 * L2 + 1, M = 2 * LO + 1;
    const float* Cg = sCG + ((L1 * 3 + L2) * 3 + LO) * 25;
    float H[8][Q];
#pragma unroll
    for (int c = 0; c < 8; c++)
#pragma unroll
        for (int q = 0; q < Q; q++) H[c][q] = 0.f;
#pragma unroll
    for (int d = 0; d < 8; d++) {
        float Wc[8];
        ((float4*)Wc)[0] = ((const float4*)(Wt + d * 8))[0];
        ((float4*)Wc)[1] = ((const float4*)(Wt + d * 8))[1];
#pragma unroll
        for (int c = 0; c < 8; c++)
#pragma unroll
            for (int q = 0; q < Q; q++) H[c][q] = fmaf(Wc[c], B[d * Q + q], H[c][q]);
    }
#pragma unroll
    for (int p = 0; p < P; p++) {
        float Pq[Q];
#pragma unroll
        for (int q = 0; q < Q; q++) Pq[q] = 0.f;
#pragma unroll
        for (int c = 0; c < 8; c++) {
            float a = A[c * P + p];
#pragma unroll
            for (int q = 0; q < Q; q++) Pq[q] = fmaf(a, H[c][q], Pq[q]);
        }
#pragma unroll
        for (int q = 0; q < Q; q++) {
            constexpr int base = LO - L1 - L2;
            int mi = p + q + base;
            if (mi >= 0 && mi < M) acc[mi] = fmaf(Cg[p * 5 + q], Pq[q], acc[mi]);
        }
    }
}

template <int L1, int L2, int LO>
__device__ __forceinline__ void path_rs(float* __restrict__ acc,
                                        const float (&A)[8 * (2 * L1 + 1)],
                                        const float* __restrict__ sB,
                                        const float* __restrict__ Wt,
                                        const float* __restrict__ sCG) {
    constexpr int P = 2 * L1 + 1, Q = 2 * L2 + 1, M = 2 * LO + 1;
    const float* Cg = sCG + ((L1 * 3 + L2) * 3 + LO) * 25;
    float H[8][Q];
#pragma unroll
    for (int c = 0; c < 8; c++)
#pragma unroll
        for (int q = 0; q < Q; q++) H[c][q] = 0.f;
#pragma unroll
    for (int d = 0; d < 4; d++) {
        float Bq[Q];
#pragma unroll
        for (int q = 0; q < Q; q++) Bq[q] = sB[d * Q + q];
        float Wc[8];
        ((float4*)Wc)[0] = ((const float4*)(Wt + d * 8))[0];
        ((float4*)Wc)[1] = ((const float4*)(Wt + d * 8))[1];
#pragma unroll
        for (int c = 0; c < 8; c++)
#pragma unroll
            for (int q = 0; q < Q; q++) H[c][q] = fmaf(Wc[c], Bq[q], H[c][q]);
    }
#pragma unroll
    for (int p = 0; p < P; p++) {
        float Pq[Q];
#pragma unroll
        for (int q = 0; q < Q; q++) Pq[q] = 0.f;
#pragma unroll
        for (int c = 0; c < 8; c++) {
            float a = A[c * P + p];
#pragma unroll
            for (int q = 0; q < Q; q++) Pq[q] = fmaf(a, H[c][q], Pq[q]);
        }
#pragma unroll
        for (int q = 0; q < Q; q++) {
            constexpr int base = LO - L1 - L2;
            int mi = p + q + base;
            if (mi >= 0 && mi < M) acc[mi] = fmaf(Cg[p * 5 + q], Pq[q], acc[mi]);
        }
    }
}

template <int L1, int L2, int LO>
__device__ __forceinline__ void path_xr(float* __restrict__ acc,
                                        const float (&A)[4 * (2 * L1 + 1)],
                                        const float* __restrict__ sBy,
                                        const float* __restrict__ Wt,
                                        const float* __restrict__ sCG) {
    constexpr int P = 2 * L1 + 1, Q = 2 * L2 + 1, M = 2 * LO + 1;
    const float* Cg = sCG + ((L1 * 3 + L2) * 3 + LO) * 25;
    float H[4][Q];
#pragma unroll
    for (int c = 0; c < 4; c++)
#pragma unroll
        for (int q = 0; q < Q; q++) H[c][q] = 0.f;
#pragma unroll
    for (int d = 0; d < 8; d++) {
        float Bq[Q];
#pragma unroll
        for (int q = 0; q < Q; q++) Bq[q] = sBy[q * 8 + d];
        float Wc[4];
        ((float4*)Wc)[0] = ((const float4*)(Wt + d * 4))[0];
#pragma unroll
        for (int c = 0; c < 4; c++)
#pragma unroll
            for (int q = 0; q < Q; q++) H[c][q] = fmaf(Wc[c], Bq[q], H[c][q]);
    }
#pragma unroll
    for (int p = 0; p < P; p++) {
        float Pq[Q];
#pragma unroll
        for (int q = 0; q < Q; q++) Pq[q] = 0.f;
#pragma unroll
        for (int c = 0; c < 4; c++) {
            float a = A[c * P + p];
#pragma unroll
            for (int q = 0; q < Q; q++) Pq[q] = fmaf(a, H[c][q], Pq[q]);
        }
#pragma unroll
        for (int q = 0; q < Q; q++) {
            constexpr int base = LO - L1 - L2;
            int mi = p + q + base;
            if (mi >= 0 && mi < M) acc[mi] = fmaf(Cg[p * 5 + q], Pq[q], acc[mi]);
        }
    }
}

template <int L1, int L2, int LO>
__device__ __forceinline__ void path_ys(float* __restrict__ acc,
                                        const float* __restrict__ sAy,
                                        const float* __restrict__ sBx,
                                        const float* __restrict__ Wt,
                                        const float* __restrict__ sCG) {
    constexpr int P = 2 * L1 + 1, Q = 2 * L2 + 1, M = 2 * LO + 1;
    const float* Cg = sCG + ((L1 * 3 + L2) * 3 + LO) * 25;
    float H[8][Q];
#pragma unroll
    for (int c = 0; c < 8; c++)
#pragma unroll
        for (int q = 0; q < Q; q++) H[c][q] = 0.f;
#pragma unroll
    for (int d = 0; d < 4; d++) {
        float Bq[Q];
#pragma unroll
        for (int q = 0; q < Q; q++) Bq[q] = sBx[d * Q + q];
        float Wc[8];
        ((float4*)Wc)[0] = ((const float4*)(Wt + d * 8))[0];
        ((float4*)Wc)[1] = ((const float4*)(Wt + d * 8))[1];
#pragma unroll
        for (int c = 0; c < 8; c++)
#pragma unroll
            for (int q = 0; q < Q; q++) H[c][q] = fmaf(Wc[c], Bq[q], H[c][q]);
    }
#pragma unroll
    for (int p = 0; p < P; p++) {
        float Pq[Q];
#pragma unroll
        for (int q = 0; q < Q; q++) Pq[q] = 0.f;
#pragma unroll
        for (int c = 0; c < 8; c++) {
            float a = sAy[p * 8 + c];
#pragma unroll
            for (int q = 0; q < Q; q++) Pq[q] = fmaf(a, H[c][q], Pq[q]);
        }
#pragma unroll
        for (int q = 0; q < Q; q++) {
            constexpr int base = LO - L1 - L2;
            int mi = p + q + base;
            if (mi >= 0 && mi < M) acc[mi] = fmaf(Cg[p * 5 + q], Pq[q], acc[mi]);
        }
    }
}

// A = y smem ([p*8+c]), B = y smem ([q*8+d]), both 8ch
template <int L1, int L2, int LO>
__device__ __forceinline__ void path_yyss(float* __restrict__ acc,
                                          const float* __restrict__ sAy,
                                          const float* __restrict__ sBy,
                                          const float* __restrict__ Wt,
                                          const float* __restrict__ sCG) {
    constexpr int P = 2 * L1 + 1, Q = 2 * L2 + 1, M = 2 * LO + 1;
    const float* Cg = sCG + ((L1 * 3 + L2) * 3 + LO) * 25;
    float H[8][Q];
#pragma unroll
    for (int c = 0; c < 8; c++)
#pragma unroll
        for (int q = 0; q < Q; q++) H[c][q] = 0.f;
#pragma unroll
    for (int d = 0; d < 8; d++) {
        float Bq[Q];
#pragma unroll
        for (int q = 0; q < Q; q++) Bq[q] = sBy[q * 8 + d];
        float Wc[8];
        ((float4*)Wc)[0] = ((const float4*)(Wt + d * 8))[0];
        ((float4*)Wc)[1] = ((const float4*)(Wt + d * 8))[1];
#pragma unroll
        for (int c = 0; c < 8; c++)
#pragma unroll
            for (int q = 0; q < Q; q++) H[c][q] = fmaf(Wc[c], Bq[q], H[c][q]);
    }
#pragma unroll
    for (int p = 0; p < P; p++) {
        float Pq[Q];
#pragma unroll
        for (int q = 0; q < Q; q++) Pq[q] = 0.f;
#pragma unroll
        for (int c = 0; c < 8; c++) {
            float a = sAy[p * 8 + c];
#pragma unroll
            for (int q = 0; q < Q; q++) Pq[q] = fmaf(a, H[c][q], Pq[q]);
        }
#pragma unroll
        for (int q = 0; q < Q; q++) {
            constexpr int base = LO - L1 - L2;
            int mi = p + q + base;
            if (mi >= 0 && mi < M) acc[mi] = fmaf(Cg[p * 5 + q], Pq[q], acc[mi]);
        }
    }
}

template <int L1, int L2, int LO>
__device__ __forceinline__ void path_xx(float* __restrict__ acc,
                                        const float (&A)[4 * (2 * L1 + 1)],
                                        const float* __restrict__ sBx,
                                        const float* __restrict__ Wt,
                                        const float* __restrict__ sCG) {
    constexpr int P = 2 * L1 + 1, Q = 2 * L2 + 1, M = 2 * LO + 1;
    const float* Cg = sCG + ((L1 * 3 + L2) * 3 + LO) * 25;
    float H[4][Q];
#pragma unroll
    for (int c = 0; c < 4; c++)
#pragma unroll
        for (int q = 0; q < Q; q++) H[c][q] = 0.f;
#pragma unroll
    for (int d = 0; d < 4; d++) {
        float Bq[Q];
#pragma unroll
        for (int q = 0; q < Q; q++) Bq[q] = sBx[d * Q + q];
        float Wc[4];
        ((float4*)Wc)[0] = ((const float4*)(Wt + d * 4))[0];
#pragma unroll
        for (int c = 0; c < 4; c++)
#pragma unroll
            for (int q = 0; q < Q; q++) H[c][q] = fmaf(Wc[c], Bq[q], H[c][q]);
    }
#pragma unroll
    for (int p = 0; p < P; p++) {
        float Pq[Q];
#pragma unroll
        for (int q = 0; q < Q; q++) Pq[q] = 0.f;
#pragma unroll
        for (int c = 0; c < 4; c++) {
            float a = A[c * P + p];
#pragma unroll
            for (int q = 0; q < Q; q++) Pq[q] = fmaf(a, H[c][q], Pq[q]);
        }
#pragma unroll
        for (int q = 0; q < Q; q++) {
            constexpr int base = LO - L1 - L2;
            int mi = p + q + base;
            if (mi >= 0 && mi < M) acc[mi] = fmaf(Cg[p * 5 + q], Pq[q], acc[mi]);
        }
    }
}

// ---------------------------------------------------------------------------
// Fused kernel: blocks [0, XXB) compute x(x)x paths -> write out;
//               blocks [XXB, XXB+EDGEB) do the atomic edge scatter.
// No data dependency between the halves (xx uses only x; edge writes g_ybuf).
// ---------------------------------------------------------------------------
#define XXB 938
#define EDGEB 1875

__device__ __forceinline__ void red4(float* p, float a, float b, float c, float d) {
    asm volatile("red.global.add.v4.f32 [%0], {%1,%2,%3,%4};"
                 :: "l"(p), "f"(a), "f"(b), "f"(c), "f"(d) : "memory");
}

__global__ __launch_bounds__(256)
void edge_xx_kernel(const float* __restrict__ x0,
                    const float* __restrict__ x1,
                    const float* __restrict__ x2,
                    const float* __restrict__ ev,
                    const int* __restrict__ eidx,
                    float* __restrict__ out) {
    __shared__ float s_x[32 * 37];
    __shared__ float s_cg[27 * 25];

    int tid = threadIdx.x;

    if (blockIdx.x >= XXB) {
        // ---------------- edge scatter part ----------------
        int e = (blockIdx.x - XXB) * 256 + tid;
        if (e >= N_EDGES) return;
        int src = eidx[e];
        int dst = eidx[N_EDGES + e];
        float2 ee = *(const float2*)(ev + 2 * e);
        float* yb = g_ybuf + (size_t)dst * 72;

        {
            float4 a = *(const float4*)(x0 + (size_t)src * 4);
            red4(yb + 0, ee.x * a.x, ee.x * a.y, ee.x * a.z, ee.x * a.w);
            red4(yb + 4, ee.y * a.x, ee.y * a.y, ee.y * a.z, ee.y * a.w);
        }
        {
            float v[12];
            const float4* p = (const float4*)(x1 + (size_t)src * 12);
            ((float4*)v)[0] = p[0];
            ((float4*)v)[1] = p[1];
            ((float4*)v)[2] = p[2];
#pragma unroll
            for (int m = 0; m < 3; m++) {
                red4(yb + 8 + m * 8,
                     ee.x * v[0 * 3 + m], ee.x * v[1 * 3 + m],
                     ee.x * v[2 * 3 + m], ee.x * v[3 * 3 + m]);
                red4(yb + 8 + m * 8 + 4,
                     ee.y * v[0 * 3 + m], ee.y * v[1 * 3 + m],
                     ee.y * v[2 * 3 + m], ee.y * v[3 * 3 + m]);
            }
        }
        {
            float v[20];
            const float4* p = (const float4*)(x2 + (size_t)src * 20);
            ((float4*)v)[0] = p[0];
            ((float4*)v)[1] = p[1];
            ((float4*)v)[2] = p[2];
            ((float4*)v)[3] = p[3];
            ((float4*)v)[4] = p[4];
#pragma unroll
            for (int m = 0; m < 5; m++) {
                red4(yb + 32 + m * 8,
                     ee.x * v[0 * 5 + m], ee.x * v[1 * 5 + m],
                     ee.x * v[2 * 5 + m], ee.x * v[3 * 5 + m]);
                red4(yb + 32 + m * 8 + 4,
                     ee.y * v[0 * 5 + m], ee.y * v[1 * 5 + m],
                     ee.y * v[2 * 5 + m], ee.y * v[3 * 5 + m]);
            }
        }
        return;
    }

    // ---------------- xx compute part: 32 nodes x 8 o per block -------------
    int nblk = blockIdx.x * 32;
    for (int i = tid; i < 32 * 36; i += 256) {
        int nl = i / 36, j = i % 36;
        int gn = nblk + nl;
        float v = 0.f;
        if (gn < N_NODES) {
            if (j < 4)       v = x0[(size_t)gn * 4 + j];
            else if (j < 16) v = x1[(size_t)gn * 12 + (j - 4)];
            else             v = x2[(size_t)gn * 20 + (j - 16)];
        }
        s_x[nl * 37 + j] = v;
    }
    for (int i = tid; i < 27 * 25; i += 256) s_cg[i] = g_cg2[i];
    __syncthreads();

    int nl = tid >> 3;
    int o = tid & 7;
    int n = nblk + nl;
    if (n >= N_NODES) return;

    const float* sx = s_x + nl * 37;
    float X0[4], X1[12], X2[20];
#pragma unroll
    for (int j = 0; j < 4; j++)  X0[j] = sx[j];
#pragma unroll
    for (int j = 0; j < 12; j++) X1[j] = sx[4 + j];
#pragma unroll
    for (int j = 0; j < 20; j++) X2[j] = sx[16 + j];

    float acc0[1] = {0.f};
    float acc1[3] = {0.f, 0.f, 0.f};
    float acc2[5] = {0.f, 0.f, 0.f, 0.f, 0.f};

    const float* wxx = g_wt + 9472 + o * 176;
    path_xx<0,0,0>(acc0, X0, sx + 0,  wxx + 0,   s_cg);
    path_xx<1,1,0>(acc0, X1, sx + 4,  wxx + 16,  s_cg);
    path_xx<2,2,0>(acc0, X2, sx + 16, wxx + 32,  s_cg);
    path_xx<1,0,1>(acc1, X1, sx + 0,  wxx + 48,  s_cg);
    path_xx<1,1,1>(acc1, X1, sx + 4,  wxx + 64,  s_cg);
    path_xx<2,1,1>(acc1, X2, sx + 4,  wxx + 80,  s_cg);
    path_xx<2,2,1>(acc1, X2, sx + 16, wxx + 96,  s_cg);
    path_xx<2,0,2>(acc2, X2, sx + 0,  wxx + 112, s_cg);
    path_xx<1,1,2>(acc2, X1, sx + 4,  wxx + 128, s_cg);
    path_xx<2,1,2>(acc2, X2, sx + 4,  wxx + 144, s_cg);
    path_xx<2,2,2>(acc2, X2, sx + 16, wxx + 160, s_cg);

    out[n * 8 + o] = acc0[0];
    float* o1 = out + 240000 + ((size_t)n * 8 + o) * 3;
    o1[0] = acc1[0]; o1[1] = acc1[1]; o1[2] = acc1[2];
    float* o2 = out + 960000 + ((size_t)n * 8 + o) * 5;
    o2[0] = acc2[0]; o2[1] = acc2[1]; o2[2] = acc2[2]; o2[3] = acc2[3]; o2[4] = acc2[4];
}

// ---------------------------------------------------------------------------
// Node kernel: yy + yx only, accumulating into out (xx already written).
// Halves rebalanced: half0 = yy \ {(0,0,0),(2,2,0)} + yx pk12  (~2840 FMA)
//                    half1 = 14 yx + yy (0,0,0) + yy (2,2,0)   (~2900 FMA)
// ---------------------------------------------------------------------------
#define SY_STRIDE 73
#define SX_STRIDE 37
#define NPB 8   // nodes per block

__global__ __launch_bounds__(128, 3)
void node_kernel(const float* __restrict__ x0, const float* __restrict__ x1,
                 const float* __restrict__ x2, float* __restrict__ out) {
    __shared__ float s_y[NPB * SY_STRIDE];
    __shared__ float s_x[NPB * SX_STRIDE];
    __shared__ float s_cg[27 * 25];
    __shared__ float s_acc[NPB * 8 * 9];   // [(o*NPB+nl)*9 + k]

    int tid = threadIdx.x;
    int nblk = blockIdx.x * NPB;

    for (int i = tid; i < NPB * 72; i += 128) {
        int nl = i / 72, j = i % 72;
        s_y[nl * SY_STRIDE + j] = g_ybuf[(size_t)(nblk + nl) * 72 + j];
    }
    for (int i = tid; i < NPB * 36; i += 128) {
        int nl = i / 36, j = i % 36;
        int gn = nblk + nl;
        float v;
        if (j < 4)       v = x0[(size_t)gn * 4 + j];
        else if (j < 16) v = x1[(size_t)gn * 12 + (j - 4)];
        else             v = x2[(size_t)gn * 20 + (j - 16)];
        s_x[nl * SX_STRIDE + j] = v;
    }
    for (int i = tid; i < 27 * 25; i += 128) s_cg[i] = g_cg2[i];
    __syncthreads();

    int half = tid >> 6;
    int ht = tid & 63;
    int nl = ht & 7;
    int o = ht >> 3;
    int n = nblk + nl;

    const float* sy = s_y + nl * SY_STRIDE;
    const float* sx = s_x + nl * SX_STRIDE;

    float acc0[1] = {0.f};
    float acc1[3] = {0.f, 0.f, 0.f};
    float acc2[5] = {0.f, 0.f, 0.f, 0.f, 0.f};

    if (half == 0) {
        float Y0[8], Y1[24], Y2[40];
#pragma unroll
        for (int c = 0; c < 8; c++) Y0[c] = sy[c];
#pragma unroll
        for (int c = 0; c < 8; c++)
#pragma unroll
            for (int q = 0; q < 3; q++) Y1[c * 3 + q] = sy[8 + q * 8 + c];
#pragma unroll
        for (int c = 0; c < 8; c++)
#pragma unroll
            for (int q = 0; q < 5; q++) Y2[c * 5 + q] = sy[32 + q * 8 + c];

        const float* wyy = g_wt + o * 704;
        path_rr<1,1,0>(acc0, Y1, Y1, wyy + 64,  s_cg);
        path_rr<1,0,1>(acc1, Y1, Y0, wyy + 192, s_cg);
        path_rr<1,1,1>(acc1, Y1, Y1, wyy + 256, s_cg);
        path_rr<2,1,1>(acc1, Y2, Y1, wyy + 320, s_cg);
        path_rr<2,2,1>(acc1, Y2, Y2, wyy + 384, s_cg);
        path_rr<2,0,2>(acc2, Y2, Y0, wyy + 448, s_cg);
        path_rr<1,1,2>(acc2, Y1, Y1, wyy + 512, s_cg);
        path_rr<2,1,2>(acc2, Y2, Y1, wyy + 576, s_cg);
        path_rr<2,2,2>(acc2, Y2, Y2, wyy + 640, s_cg);

        const float* wyx = g_wt + 5632 + o * 480;
        path_rs<2,0,2>(acc2, Y2, sx + 0, wyx + 12 * 32, s_cg);
    } else {
        float X0[4], X1[12], X2[20];
#pragma unroll
        for (int j = 0; j < 4; j++)  X0[j] = sx[j];
#pragma unroll
        for (int j = 0; j < 12; j++) X1[j] = sx[4 + j];
#pragma unroll
        for (int j = 0; j < 20; j++) X2[j] = sx[16 + j];

        const float* wyx = g_wt + 5632 + o * 480;
        path_xr<0,0,0>(acc0, X0, sy + 0,  wyx + 0 * 32,  s_cg);
        path_xr<1,1,0>(acc0, X1, sy + 8,  wyx + 1 * 32,  s_cg);
        path_xr<2,2,0>(acc0, X2, sy + 32, wyx + 2 * 32,  s_cg);
        path_xr<1,0,1>(acc1, X1, sy + 0,  wyx + 3 * 32,  s_cg);
        path_ys<1,0,1>(acc1, sy + 8,  sx + 0,  wyx + 4 * 32,  s_cg);
        path_xr<1,1,1>(acc1, X1, sy + 8,  wyx + 5 * 32,  s_cg);
        path_xr<2,1,1>(acc1, X2, sy + 8,  wyx + 6 * 32,  s_cg);
        path_ys<2,1,1>(acc1, sy + 32, sx + 4,  wyx + 7 * 32,  s_cg);
        path_xr<2,2,1>(acc1, X2, sy + 32, wyx + 8 * 32,  s_cg);
        path_xr<2,0,2>(acc2, X2, sy + 0,  wyx + 9 * 32,  s_cg);
        path_xr<1,1,2>(acc2, X1, sy + 8,  wyx + 10 * 32, s_cg);
        path_xr<2,1,2>(acc2, X2, sy + 8,  wyx + 11 * 32, s_cg);
        path_ys<2,1,2>(acc2, sy + 32, sx + 4,  wyx + 13 * 32, s_cg);
        path_xr<2,2,2>(acc2, X2, sy + 32, wyx + 14 * 32, s_cg);

        // moved yy paths (smem-smem)
        const float* wyy = g_wt + o * 704;
        path_yyss<0,0,0>(acc0, sy + 0,  sy + 0,  wyy + 0,   s_cg);
        path_yyss<2,2,0>(acc0, sy + 32, sy + 32, wyy + 128, s_cg);
    }

    float* sa = s_acc + (o * NPB + nl) * 9;
    if (half == 1) {
        sa[0] = acc0[0];
        sa[1] = acc1[0]; sa[2] = acc1[1]; sa[3] = acc1[2];
        sa[4] = acc2[0]; sa[5] = acc2[1]; sa[6] = acc2[2];
        sa[7] = acc2[3]; sa[8] = acc2[4];
    }
    __syncthreads();
    if (half == 0) {
        // accumulate into out (xx part already there)
        float* p0 = out + n * 8 + o;
        *p0 += acc0[0] + sa[0];
        float* o1 = out + 240000 + ((size_t)n * 8 + o) * 3;
        o1[0] += acc1[0] + sa[1]; o1[1] += acc1[1] + sa[2]; o1[2] += acc1[2] + sa[3];
        float* o2 = out + 960000 + ((size_t)n * 8 + o) * 5;
        o2[0] += acc2[0] + sa[4]; o2[1] += acc2[1] + sa[5]; o2[2] += acc2[2] + sa[6];
        o2[3] += acc2[3] + sa[7]; o2[4] += acc2[4] + sa[8];
    }
}

// ---------------------------------------------------------------------------
extern "C" void kernel_launch(void* const* d_in, const int* in_sizes, int n_in,
                              void* d_out, int out_size) {
    const float* x0   = (const float*)d_in[0];
    const float* x1   = (const float*)d_in[1];
    const float* x2   = (const float*)d_in[2];
    const float* ev   = (const float*)d_in[3];
    const float* Wxx0 = (const float*)d_in[4];
    const float* Wxx1 = (const float*)d_in[5];
    const float* Wxx2 = (const float*)d_in[6];
    const float* Wyx0 = (const float*)d_in[7];
    const float* Wyx1 = (const float*)d_in[8];
    const float* Wyx2 = (const float*)d_in[9];
    const float* Wyy0 = (const float*)d_in[10];
    const float* Wyy1 = (const float*)d_in[11];
    const float* Wyy2 = (const float*)d_in[12];
    const int* eidx   = (const int*)d_in[13];
    float* out = (float*)d_out;

    zero_kernel<<<(N_NODES * 18 + 255) / 256, 256>>>();
    cg_init_kernel<<<27, 25>>>();
    wt_init_kernel<<<(10880 + 255) / 256, 256>>>(Wyy0, Wyy1, Wyy2,
                                                 Wyx0, Wyx1, Wyx2,
                                                 Wxx0, Wxx1, Wxx2);
    edge_xx_kernel<<<XXB + EDGEB, 256>>>(x0, x1, x2, ev, eidx, out);
    node_kernel<<<N_NODES / NPB, 128>>>(x0, x1, x2, out);
}

// round 13
// speedup vs baseline: 1.2102x; 1.2102x over previous
#include <cuda_runtime.h>

#define N_NODES 30000
#define N_EDGES 480000

// ---------------------------------------------------------------------------
// Compile-time Clebsch-Gordan coefficients (same algorithm as reference,
// evaluated in double at compile time -> identical float values).
// ---------------------------------------------------------------------------
constexpr double cfac(int n) {
    double r = 1.0;
    for (int i = 2; i <= n; i++) r *= (double)i;
    return r;
}
constexpr double csqrt_(double x) {
    double g = x > 1.0 ? x : 1.0;
    for (int i = 0; i < 64; i++) g = 0.5 * (g + x / g);
    return g;
}
constexpr double cg_c(int j1, int m1, int j2, int m2, int j, int m) {
    if (m != m1 + m2) return 0.0;
    int dj = j1 - j2 < 0 ? j2 - j1 : j1 - j2;
    if (j < dj || j > j1 + j2) return 0.0;
    double pre = csqrt_((2.0 * j + 1.0) * cfac(j + j1 - j2) * cfac(j - j1 + j2) *
                        cfac(j1 + j2 - j) / cfac(j1 + j2 + j + 1));
    pre *= csqrt_(cfac(j + m) * cfac(j - m) * cfac(j1 - m1) * cfac(j1 + m1) *
                  cfac(j2 - m2) * cfac(j2 + m2));
    double s = 0.0;
    for (int k = 0; k <= j1 + j2 - j; k++) {
        int d0 = k;
        int d1 = j1 + j2 - j - k;
        int d2 = j1 - m1 - k;
        int d3 = j2 + m2 - k;
        int d4 = j - j2 + m1 + k;
        int d5 = j - j1 - m2 + k;
        if (d0 < 0 || d1 < 0 || d2 < 0 || d3 < 0 || d4 < 0 || d5 < 0) continue;
        double den = cfac(d0) * cfac(d1) * cfac(d2) * cfac(d3) * cfac(d4) * cfac(d5);
        s += ((k & 1) ? -1.0 : 1.0) / den;
    }
    return pre * s;
}

// Per-(path, p, q) coefficient with selection rule m = p+q+LO-L1-L2.
template <int L1, int L2, int LO, int PP, int QQ>
struct CGV {
    static constexpr int MI = PP + QQ + LO - L1 - L2;
    static constexpr bool IN =
        (PP <= 2 * L1) && (QQ <= 2 * L2) && (MI >= 0) && (MI <= 2 * LO);
    static constexpr float v =
        IN ? (float)cg_c(L1, PP - L1, L2, QQ - L2, LO, MI - LO) : 0.0f;
};

// ---------------------------------------------------------------------------
// Scratch (static device globals — no allocation)
// y layout per node: [l-block][m][ch(8)] -> l=0 @0, l=1 @8, l=2 @32. 72 f/node.
// ---------------------------------------------------------------------------
__device__ __align__(16) float g_ybuf[N_NODES * 72];

// Orientation-optimized fused weights, layout per path [d*CA + c] (c = A-side
// channel, fastest). Regions: yy 11 paths (o-stride 704) @0; yx 15 paths
// (o-stride 480) @5632; xx 11 paths (o-stride 176) @9472.
__device__ __align__(16) float g_wt[10880];

// ---------------------------------------------------------------------------
// Kernel 1: zero y accumulator
// ---------------------------------------------------------------------------
__global__ void zero_kernel() {
    int i = blockIdx.x * blockDim.x + threadIdx.x;
    if (i < N_NODES * 18) {
        ((float4*)g_ybuf)[i] = make_float4(0.f, 0.f, 0.f, 0.f);
    }
}

// ---------------------------------------------------------------------------
// Kernel 2b: fused + orientation-optimized weight table (as round 9)
// ---------------------------------------------------------------------------
__global__ void wt_init_kernel(const float* __restrict__ wyy0, const float* __restrict__ wyy1,
                               const float* __restrict__ wyy2, const float* __restrict__ wyx0,
                               const float* __restrict__ wyx1, const float* __restrict__ wyx2,
                               const float* __restrict__ wxx0, const float* __restrict__ wxx1,
                               const float* __restrict__ wxx2) {
    int t = blockIdx.x * blockDim.x + threadIdx.x;
    if (t >= 10880) return;

    const int  loF[11]  = {0, 0, 0, 1, 1, 1, 1, 2, 2, 2, 2};
    const int  kaF[11]  = {0, 1, 2, 1, 2, 4, 5, 3, 1, 4, 5};
    const int  kbF[11]  = {-1, -1, -1, 0, -1, 3, -1, 0, -1, 2, -1};
    const float sgF[11] = {0.f, 0.f, 0.f, 1.f, 0.f, 1.f, 0.f, 1.f, 0.f, -1.f, 0.f};

    float val;
    if (t < 5632) {                       // yy fused, CA=CB=8
        int o = t / 704, v = t % 704;
        int pk = v / 64, w = v % 64, d = w / 8, c = w % 8;
        const float* S[3] = {wyy0, wyy1, wyy2};
        const float* src = S[loF[pk]];
        val = src[(kaF[pk] * 64 + c * 8 + d) * 8 + o];
        if (kbF[pk] >= 0)
            val += sgF[pk] * src[(kbF[pk] * 64 + d * 8 + c) * 8 + o];
    } else if (t < 9472) {                // yx, 15 paths, per-path orientation
        int u = t - 5632;
        int o = u / 480, v = u % 480;
        int pk = v / 32, w = v % 32;
        const int  loX[15]  = {0,0,0, 1,1,1,1,1,1, 2,2,2,2,2,2};
        const int  kX[15]   = {0,1,2, 0,1,2,3,4,5, 0,1,2,3,4,5};
        const int  axF[15]  = {1,1,1, 1,0,1,1,0,1, 1,1,1,0,0,1};
        const float sgX[15] = {1.f,1.f,1.f, 1.f,0.f,-1.f,1.f,0.f,-1.f,
                               1.f,1.f,-1.f,0.f,0.f,1.f};
        const float* S[3] = {wyx0, wyx1, wyx2};
        const float* src = S[loX[pk]];
        if (axF[pk]) {                    // A=x: same linear index, sign-scaled
            val = sgX[pk] * src[(kX[pk] * 32 + w) * 8 + o];
        } else {                          // A=y: transpose c,d
            int d = w / 8, c = w % 8;
            val = src[(kX[pk] * 32 + c * 4 + d) * 8 + o];
        }
    } else {                              // xx fused, CA=CB=4
        int u = t - 9472;
        int o = u / 176, v = u % 176;
        int pk = v / 16, w = v % 16, d = w / 4, c = w % 4;
        const float* S[3] = {wxx0, wxx1, wxx2};
        const float* src = S[loF[pk]];
        val = src[(kaF[pk] * 16 + c * 4 + d) * 8 + o];
        if (kbF[pk] >= 0)
            val += sgF[pk] * src[(kbF[pk] * 16 + d * 4 + c) * 8 + o];
    }
    g_wt[t] = val;
}

// ---------------------------------------------------------------------------
// Kernel 3: edge gather / outer-product / scatter-add (vector atomics)
// ---------------------------------------------------------------------------
__device__ __forceinline__ void red4(float* p, float a, float b, float c, float d) {
    asm volatile("red.global.add.v4.f32 [%0], {%1,%2,%3,%4};"
                 :: "l"(p), "f"(a), "f"(b), "f"(c), "f"(d) : "memory");
}

__global__ void edge_kernel(const float* __restrict__ x0,
                            const float* __restrict__ x1,
                            const float* __restrict__ x2,
                            const float* __restrict__ ev,
                            const int* __restrict__ eidx) {
    int e = blockIdx.x * blockDim.x + threadIdx.x;
    if (e >= N_EDGES) return;
    int src = eidx[e];
    int dst = eidx[N_EDGES + e];
    float2 ee = *(const float2*)(ev + 2 * e);
    float* yb = g_ybuf + (size_t)dst * 72;

    {
        float4 a = *(const float4*)(x0 + (size_t)src * 4);
        red4(yb + 0, ee.x * a.x, ee.x * a.y, ee.x * a.z, ee.x * a.w);
        red4(yb + 4, ee.y * a.x, ee.y * a.y, ee.y * a.z, ee.y * a.w);
    }
    {
        float v[12];
        const float4* p = (const float4*)(x1 + (size_t)src * 12);
        ((float4*)v)[0] = p[0];
        ((float4*)v)[1] = p[1];
        ((float4*)v)[2] = p[2];
#pragma unroll
        for (int m = 0; m < 3; m++) {
            red4(yb + 8 + m * 8,
                 ee.x * v[0 * 3 + m], ee.x * v[1 * 3 + m],
                 ee.x * v[2 * 3 + m], ee.x * v[3 * 3 + m]);
            red4(yb + 8 + m * 8 + 4,
                 ee.y * v[0 * 3 + m], ee.y * v[1 * 3 + m],
                 ee.y * v[2 * 3 + m], ee.y * v[3 * 3 + m]);
        }
    }
    {
        float v[20];
        const float4* p = (const float4*)(x2 + (size_t)src * 20);
        ((float4*)v)[0] = p[0];
        ((float4*)v)[1] = p[1];
        ((float4*)v)[2] = p[2];
        ((float4*)v)[3] = p[3];
        ((float4*)v)[4] = p[4];
#pragma unroll
        for (int m = 0; m < 5; m++) {
            red4(yb + 32 + m * 8,
                 ee.x * v[0 * 5 + m], ee.x * v[1 * 5 + m],
                 ee.x * v[2 * 5 + m], ee.x * v[3 * 5 + m]);
            red4(yb + 32 + m * 8 + 4,
                 ee.y * v[0 * 5 + m], ee.y * v[1 * 5 + m],
                 ee.y * v[2 * 5 + m], ee.y * v[3 * 5 + m]);
        }
    }
}

// ---------------------------------------------------------------------------
// Node-kernel path machinery. H stage as before; P/CG stage uses compile-time
// CG immediates with structural-zero skipping:
//   H[c][q] = sum_d W[d*CA+c] * B[d,q]
//   for (p,q) with CG != 0: Pq = sum_c A[c,p]*H[c][q]; acc[m] += CG * Pq
// ---------------------------------------------------------------------------

template <int L1, int L2, int LO, int CA, int PP, int QQ>
__device__ __forceinline__ void tail_q(float* __restrict__ acc,
                                       const float (&Ac)[CA],
                                       const float (&H)[CA][2 * L2 + 1]) {
    if constexpr (QQ <= 2 * L2) {
        using C = CGV<L1, L2, LO, PP, QQ>;
        if constexpr (C::v != 0.0f) {
            float Pq = 0.f;
#pragma unroll
            for (int c = 0; c < CA; c++) Pq = fmaf(Ac[c], H[c][QQ], Pq);
            acc[C::MI] = fmaf(C::v, Pq, acc[C::MI]);
        }
        tail_q<L1, L2, LO, CA, PP, QQ + 1>(acc, Ac, H);
    }
}

template <int L1, int L2, int LO, int CA, int PP, typename GA>
__device__ __forceinline__ void tail_p(float* __restrict__ acc,
                                       GA getA,
                                       const float (&H)[CA][2 * L2 + 1]) {
    if constexpr (PP <= 2 * L1) {
        float Ac[CA];
#pragma unroll
        for (int c = 0; c < CA; c++) Ac[c] = getA(c, PP);
        tail_q<L1, L2, LO, CA, PP, 0>(acc, Ac, H);
        tail_p<L1, L2, LO, CA, PP + 1, GA>(acc, getA, H);
    }
}

// yy: A, B register arrays (8ch, [c*(2l+1)+i])
template <int L1, int L2, int LO>
__device__ __forceinline__ void path_rr(float* __restrict__ acc,
                                        const float (&A)[8 * (2 * L1 + 1)],
                                        const float (&B)[8 * (2 * L2 + 1)],
                                        const float* __restrict__ Wt) {
    constexpr int P = 2 * L1 + 1, Q = 2 * L2 + 1;
    float H[8][Q];
#pragma unroll
    for (int c = 0; c < 8; c++)
#pragma unroll
        for (int q = 0; q < Q; q++) H[c][q] = 0.f;
#pragma unroll
    for (int d = 0; d < 8; d++) {
        float Wc[8];
        ((float4*)Wc)[0] = ((const float4*)(Wt + d * 8))[0];
        ((float4*)Wc)[1] = ((const float4*)(Wt + d * 8))[1];
#pragma unroll
        for (int c = 0; c < 8; c++)
#pragma unroll
            for (int q = 0; q < Q; q++) H[c][q] = fmaf(Wc[c], B[d * Q + q], H[c][q]);
    }
    tail_p<L1, L2, LO, 8, 0>(acc, [&](int c, int p) { return A[c * P + p]; }, H);
}

// A = y registers (8ch), B = x smem ([d*Q+q], 4ch)
template <int L1, int L2, int LO>
__device__ __forceinline__ void path_rs(float* __restrict__ acc,
                                        const float (&A)[8 * (2 * L1 + 1)],
                                        const float* __restrict__ sB,
                                        const float* __restrict__ Wt) {
    constexpr int P = 2 * L1 + 1, Q = 2 * L2 + 1;
    float H[8][Q];
#pragma unroll
    for (int c = 0; c < 8; c++)
#pragma unroll
        for (int q = 0; q < Q; q++) H[c][q] = 0.f;
#pragma unroll
    for (int d = 0; d < 4; d++) {
        float Bq[Q];
#pragma unroll
        for (int q = 0; q < Q; q++) Bq[q] = sB[d * Q + q];
        float Wc[8];
        ((float4*)Wc)[0] = ((const float4*)(Wt + d * 8))[0];
        ((float4*)Wc)[1] = ((const float4*)(Wt + d * 8))[1];
#pragma unroll
        for (int c = 0; c < 8; c++)
#pragma unroll
            for (int q = 0; q < Q; q++) H[c][q] = fmaf(Wc[c], Bq[q], H[c][q]);
    }
    tail_p<L1, L2, LO, 8, 0>(acc, [&](int c, int p) { return A[c * P + p]; }, H);
}

// A = x registers (4ch), B = y smem ([q*8+d], 8ch)
template <int L1, int L2, int LO>
__device__ __forceinline__ void path_xr(float* __restrict__ acc,
                                        const float (&A)[4 * (2 * L1 + 1)],
                                        const float* __restrict__ sBy,
                                        const float* __restrict__ Wt) {
    constexpr int P = 2 * L1 + 1, Q = 2 * L2 + 1;
    float H[4][Q];
#pragma unroll
    for (int c = 0; c < 4; c++)
#pragma unroll
        for (int q = 0; q < Q; q++) H[c][q] = 0.f;
#pragma unroll
    for (int d = 0; d < 8; d++) {
        float Bq[Q];
#pragma unroll
        for (int q = 0; q < Q; q++) Bq[q] = sBy[q * 8 + d];
        float Wc[4];
        ((float4*)Wc)[0] = ((const float4*)(Wt + d * 4))[0];
#pragma unroll
        for (int c = 0; c < 4; c++)
#pragma unroll
            for (int q = 0; q < Q; q++) H[c][q] = fmaf(Wc[c], Bq[q], H[c][q]);
    }
    tail_p<L1, L2, LO, 4, 0>(acc, [&](int c, int p) { return A[c * P + p]; }, H);
}

// A = y smem ([p*8+c], 8ch), B = x smem ([d*Q+q], 4ch)
template <int L1, int L2, int LO>
__device__ __forceinline__ void path_ys(float* __restrict__ acc,
                                        const float* __restrict__ sAy,
                                        const float* __restrict__ sBx,
                                        const float* __restrict__ Wt) {
    constexpr int Q = 2 * L2 + 1;
    float H[8][Q];
#pragma unroll
    for (int c = 0; c < 8; c++)
#pragma unroll
        for (int q = 0; q < Q; q++) H[c][q] = 0.f;
#pragma unroll
    for (int d = 0; d < 4; d++) {
        float Bq[Q];
#pragma unroll
        for (int q = 0; q < Q; q++) Bq[q] = sBx[d * Q + q];
        float Wc[8];
        ((float4*)Wc)[0] = ((const float4*)(Wt + d * 8))[0];
        ((float4*)Wc)[1] = ((const float4*)(Wt + d * 8))[1];
#pragma unroll
        for (int c = 0; c < 8; c++)
#pragma unroll
            for (int q = 0; q < Q; q++) H[c][q] = fmaf(Wc[c], Bq[q], H[c][q]);
    }
    tail_p<L1, L2, LO, 8, 0>(acc, [&](int c, int p) { return sAy[p * 8 + c]; }, H);
}

// A = x registers (4ch), B = x smem ([d*Q+q], 4ch)
template <int L1, int L2, int LO>
__device__ __forceinline__ void path_xx(float* __restrict__ acc,
                                        const float (&A)[4 * (2 * L1 + 1)],
                                        const float* __restrict__ sBx,
                                        const float* __restrict__ Wt) {
    constexpr int P = 2 * L1 + 1, Q = 2 * L2 + 1;
    float H[4][Q];
#pragma unroll
    for (int c = 0; c < 4; c++)
#pragma unroll
        for (int q = 0; q < Q; q++) H[c][q] = 0.f;
#pragma unroll
    for (int d = 0; d < 4; d++) {
        float Bq[Q];
#pragma unroll
        for (int q = 0; q < Q; q++) Bq[q] = sBx[d * Q + q];
        float Wc[4];
        ((float4*)Wc)[0] = ((const float4*)(Wt + d * 4))[0];
#pragma unroll
        for (int c = 0; c < 4; c++)
#pragma unroll
            for (int q = 0; q < Q; q++) H[c][q] = fmaf(Wc[c], Bq[q], H[c][q]);
    }
    tail_p<L1, L2, LO, 4, 0>(acc, [&](int c, int p) { return A[c * P + p]; }, H);
}

#define SY_STRIDE 73
#define SX_STRIDE 37
#define NPB 8   // nodes per block

__global__ __launch_bounds__(128, 3)
void node_kernel(const float* __restrict__ x0, const float* __restrict__ x1,
                 const float* __restrict__ x2, float* __restrict__ out) {
    __shared__ float s_y[NPB * SY_STRIDE];
    __shared__ float s_x[NPB * SX_STRIDE];
    __shared__ float s_acc[NPB * 8 * 9];   // [(o*NPB+nl)*9 + k]

    int tid = threadIdx.x;
    int nblk = blockIdx.x * NPB;

    for (int i = tid; i < NPB * 72; i += 128) {
        int nl = i / 72, j = i % 72;
        s_y[nl * SY_STRIDE + j] = g_ybuf[(size_t)(nblk + nl) * 72 + j];
    }
    for (int i = tid; i < NPB * 36; i += 128) {
        int nl = i / 36, j = i % 36;
        int gn = nblk + nl;
        float v;
        if (j < 4)       v = x0[(size_t)gn * 4 + j];
        else if (j < 16) v = x1[(size_t)gn * 12 + (j - 4)];
        else             v = x2[(size_t)gn * 20 + (j - 16)];
        s_x[nl * SX_STRIDE + j] = v;
    }
    __syncthreads();

    int half = tid >> 6;
    int ht = tid & 63;
    int nl = ht & 7;
    int o = ht >> 3;
    int n = nblk + nl;

    const float* sy = s_y + nl * SY_STRIDE;
    const float* sx = s_x + nl * SX_STRIDE;

    float acc0[1] = {0.f};
    float acc1[3] = {0.f, 0.f, 0.f};
    float acc2[5] = {0.f, 0.f, 0.f, 0.f, 0.f};

    if (half == 0) {
        float Y0[8], Y1[24], Y2[40];
#pragma unroll
        for (int c = 0; c < 8; c++) Y0[c] = sy[c];
#pragma unroll
        for (int c = 0; c < 8; c++)
#pragma unroll
            for (int q = 0; q < 3; q++) Y1[c * 3 + q] = sy[8 + q * 8 + c];
#pragma unroll
        for (int c = 0; c < 8; c++)
#pragma unroll
            for (int q = 0; q < 5; q++) Y2[c * 5 + q] = sy[32 + q * 8 + c];

        const float* wyy = g_wt + o * 704;
        path_rr<0,0,0>(acc0, Y0, Y0, wyy + 0);
        path_rr<1,1,0>(acc0, Y1, Y1, wyy + 64);
        path_rr<2,2,0>(acc0, Y2, Y2, wyy + 128);
        path_rr<1,0,1>(acc1, Y1, Y0, wyy + 192);
        path_rr<1,1,1>(acc1, Y1, Y1, wyy + 256);
        path_rr<2,1,1>(acc1, Y2, Y1, wyy + 320);
        path_rr<2,2,1>(acc1, Y2, Y2, wyy + 384);
        path_rr<2,0,2>(acc2, Y2, Y0, wyy + 448);
        path_rr<1,1,2>(acc2, Y1, Y1, wyy + 512);
        path_rr<2,1,2>(acc2, Y2, Y1, wyy + 576);
        path_rr<2,2,2>(acc2, Y2, Y2, wyy + 640);

        const float* wyx = g_wt + 5632 + o * 480;
        path_rs<2,0,2>(acc2, Y2, sx + 0, wyx + 12 * 32);
    } else {
        float X0[4], X1[12], X2[20];
#pragma unroll
        for (int j = 0; j < 4; j++)  X0[j] = sx[j];
#pragma unroll
        for (int j = 0; j < 12; j++) X1[j] = sx[4 + j];
#pragma unroll
        for (int j = 0; j < 20; j++) X2[j] = sx[16 + j];

        const float* wyx = g_wt + 5632 + o * 480;
        path_xr<0,0,0>(acc0, X0, sy + 0,  wyx + 0 * 32);
        path_xr<1,1,0>(acc0, X1, sy + 8,  wyx + 1 * 32);
        path_xr<2,2,0>(acc0, X2, sy + 32, wyx + 2 * 32);
        path_xr<1,0,1>(acc1, X1, sy + 0,  wyx + 3 * 32);
        path_ys<1,0,1>(acc1, sy + 8,  sx + 0,  wyx + 4 * 32);
        path_xr<1,1,1>(acc1, X1, sy + 8,  wyx + 5 * 32);
        path_xr<2,1,1>(acc1, X2, sy + 8,  wyx + 6 * 32);
        path_ys<2,1,1>(acc1, sy + 32, sx + 4,  wyx + 7 * 32);
        path_xr<2,2,1>(acc1, X2, sy + 32, wyx + 8 * 32);
        path_xr<2,0,2>(acc2, X2, sy + 0,  wyx + 9 * 32);
        path_xr<1,1,2>(acc2, X1, sy + 8,  wyx + 10 * 32);
        path_xr<2,1,2>(acc2, X2, sy + 8,  wyx + 11 * 32);
        path_ys<2,1,2>(acc2, sy + 32, sx + 4,  wyx + 13 * 32);
        path_xr<2,2,2>(acc2, X2, sy + 32, wyx + 14 * 32);

        const float* wxx = g_wt + 9472 + o * 176;
        path_xx<0,0,0>(acc0, X0, sx + 0,  wxx + 0);
        path_xx<1,1,0>(acc0, X1, sx + 4,  wxx + 16);
        path_xx<2,2,0>(acc0, X2, sx + 16, wxx + 32);
        path_xx<1,0,1>(acc1, X1, sx + 0,  wxx + 48);
        path_xx<1,1,1>(acc1, X1, sx + 4,  wxx + 64);
        path_xx<2,1,1>(acc1, X2, sx + 4,  wxx + 80);
        path_xx<2,2,1>(acc1, X2, sx + 16, wxx + 96);
        path_xx<2,0,2>(acc2, X2, sx + 0,  wxx + 112);
        path_xx<1,1,2>(acc2, X1, sx + 4,  wxx + 128);
        path_xx<2,1,2>(acc2, X2, sx + 4,  wxx + 144);
        path_xx<2,2,2>(acc2, X2, sx + 16, wxx + 160);
    }

    float* sa = s_acc + (o * NPB + nl) * 9;
    if (half == 1) {
        sa[0] = acc0[0];
        sa[1] = acc1[0]; sa[2] = acc1[1]; sa[3] = acc1[2];
        sa[4] = acc2[0]; sa[5] = acc2[1]; sa[6] = acc2[2];
        sa[7] = acc2[3]; sa[8] = acc2[4];
    }
    __syncthreads();
    if (half == 0) {
        out[n * 8 + o] = acc0[0] + sa[0];
        float* o1 = out + 240000 + ((size_t)n * 8 + o) * 3;
        o1[0] = acc1[0] + sa[1]; o1[1] = acc1[1] + sa[2]; o1[2] = acc1[2] + sa[3];
        float* o2 = out + 960000 + ((size_t)n * 8 + o) * 5;
        o2[0] = acc2[0] + sa[4]; o2[1] = acc2[1] + sa[5]; o2[2] = acc2[2] + sa[6];
        o2[3] = acc2[3] + sa[7]; o2[4] = acc2[4] + sa[8];
    }
}

// ---------------------------------------------------------------------------
extern "C" void kernel_launch(void* const* d_in, const int* in_sizes, int n_in,
                              void* d_out, int out_size) {
    const float* x0   = (const float*)d_in[0];
    const float* x1   = (const float*)d_in[1];
    const float* x2   = (const float*)d_in[2];
    const float* ev   = (const float*)d_in[3];
    const float* Wxx0 = (const float*)d_in[4];
    const float* Wxx1 = (const float*)d_in[5];
    const float* Wxx2 = (const float*)d_in[6];
    const float* Wyx0 = (const float*)d_in[7];
    const float* Wyx1 = (const float*)d_in[8];
    const float* Wyx2 = (const float*)d_in[9];
    const float* Wyy0 = (const float*)d_in[10];
    const float* Wyy1 = (const float*)d_in[11];
    const float* Wyy2 = (const float*)d_in[12];
    const int* eidx   = (const int*)d_in[13];
    float* out = (float*)d_out;

    zero_kernel<<<(N_NODES * 18 + 255) / 256, 256>>>();
    wt_init_kernel<<<(10880 + 255) / 256, 256>>>(Wyy0, Wyy1, Wyy2,
                                                 Wyx0, Wyx1, Wyx2,
                                                 Wxx0, Wxx1, Wxx2);
    edge_kernel<<<(N_EDGES + 255) / 256, 256>>>(x0, x1, x2, ev, eidx);
    node_kernel<<<N_NODES / NPB, 128>>>(x0, x1, x2, out);
}

// round 14
// speedup vs baseline: 1.2599x; 1.0410x over previous
#include <cuda_runtime.h>

#define N_NODES 30000
#define N_EDGES 480000

// ---------------------------------------------------------------------------
// Compile-time Clebsch-Gordan coefficients (same algorithm as reference,
// evaluated in double at compile time -> identical float values).
// ---------------------------------------------------------------------------
constexpr double cfac(int n) {
    double r = 1.0;
    for (int i = 2; i <= n; i++) r *= (double)i;
    return r;
}
constexpr double csqrt_(double x) {
    double g = x > 1.0 ? x : 1.0;
    for (int i = 0; i < 64; i++) g = 0.5 * (g + x / g);
    return g;
}
constexpr double cg_c(int j1, int m1, int j2, int m2, int j, int m) {
    if (m != m1 + m2) return 0.0;
    int dj = j1 - j2 < 0 ? j2 - j1 : j1 - j2;
    if (j < dj || j > j1 + j2) return 0.0;
    double pre = csqrt_((2.0 * j + 1.0) * cfac(j + j1 - j2) * cfac(j - j1 + j2) *
                        cfac(j1 + j2 - j) / cfac(j1 + j2 + j + 1));
    pre *= csqrt_(cfac(j + m) * cfac(j - m) * cfac(j1 - m1) * cfac(j1 + m1) *
                  cfac(j2 - m2) * cfac(j2 + m2));
    double s = 0.0;
    for (int k = 0; k <= j1 + j2 - j; k++) {
        int d0 = k;
        int d1 = j1 + j2 - j - k;
        int d2 = j1 - m1 - k;
        int d3 = j2 + m2 - k;
        int d4 = j - j2 + m1 + k;
        int d5 = j - j1 - m2 + k;
        if (d0 < 0 || d1 < 0 || d2 < 0 || d3 < 0 || d4 < 0 || d5 < 0) continue;
        double den = cfac(d0) * cfac(d1) * cfac(d2) * cfac(d3) * cfac(d4) * cfac(d5);
        s += ((k & 1) ? -1.0 : 1.0) / den;
    }
    return pre * s;
}

// Per-(path, p, q) coefficient with selection rule m = p+q+LO-L1-L2.
template <int L1, int L2, int LO, int PP, int QQ>
struct CGV {
    static constexpr int MI = PP + QQ + LO - L1 - L2;
    static constexpr bool IN =
        (PP <= 2 * L1) && (QQ <= 2 * L2) && (MI >= 0) && (MI <= 2 * LO);
    static constexpr float v =
        IN ? (float)cg_c(L1, PP - L1, L2, QQ - L2, LO, MI - LO) : 0.0f;
};

// ---------------------------------------------------------------------------
// Scratch (static device globals — no allocation)
// y layout per node: [l-block][m][ch(8)] -> l=0 @0, l=1 @8, l=2 @32. 72 f/node.
// ---------------------------------------------------------------------------
__device__ __align__(16) float g_ybuf[N_NODES * 72];

// Orientation-optimized fused weights, layout per path [d*CA + c] (c = A-side
// channel, fastest). Regions: yy 11 paths (o-stride 704) @0; yx 15 paths
// (o-stride 480) @5632; xx 11 paths (o-stride 176) @9472.
__device__ __align__(16) float g_wt[10880];

// ---------------------------------------------------------------------------
// Kernel 1: zero y accumulator
// ---------------------------------------------------------------------------
__global__ void zero_kernel() {
    int i = blockIdx.x * blockDim.x + threadIdx.x;
    if (i < N_NODES * 18) {
        ((float4*)g_ybuf)[i] = make_float4(0.f, 0.f, 0.f, 0.f);
    }
}

// ---------------------------------------------------------------------------
// Kernel 2b: fused + orientation-optimized weight table (as round 9)
// ---------------------------------------------------------------------------
__global__ void wt_init_kernel(const float* __restrict__ wyy0, const float* __restrict__ wyy1,
                               const float* __restrict__ wyy2, const float* __restrict__ wyx0,
                               const float* __restrict__ wyx1, const float* __restrict__ wyx2,
                               const float* __restrict__ wxx0, const float* __restrict__ wxx1,
                               const float* __restrict__ wxx2) {
    int t = blockIdx.x * blockDim.x + threadIdx.x;
    if (t >= 10880) return;

    const int  loF[11]  = {0, 0, 0, 1, 1, 1, 1, 2, 2, 2, 2};
    const int  kaF[11]  = {0, 1, 2, 1, 2, 4, 5, 3, 1, 4, 5};
    const int  kbF[11]  = {-1, -1, -1, 0, -1, 3, -1, 0, -1, 2, -1};
    const float sgF[11] = {0.f, 0.f, 0.f, 1.f, 0.f, 1.f, 0.f, 1.f, 0.f, -1.f, 0.f};

    float val;
    if (t < 5632) {                       // yy fused, CA=CB=8
        int o = t / 704, v = t % 704;
        int pk = v / 64, w = v % 64, d = w / 8, c = w % 8;
        const float* S[3] = {wyy0, wyy1, wyy2};
        const float* src = S[loF[pk]];
        val = src[(kaF[pk] * 64 + c * 8 + d) * 8 + o];
        if (kbF[pk] >= 0)
            val += sgF[pk] * src[(kbF[pk] * 64 + d * 8 + c) * 8 + o];
    } else if (t < 9472) {                // yx, 15 paths, per-path orientation
        int u = t - 5632;
        int o = u / 480, v = u % 480;
        int pk = v / 32, w = v % 32;
        const int  loX[15]  = {0,0,0, 1,1,1,1,1,1, 2,2,2,2,2,2};
        const int  kX[15]   = {0,1,2, 0,1,2,3,4,5, 0,1,2,3,4,5};
        const int  axF[15]  = {1,1,1, 1,0,1,1,0,1, 1,1,1,0,0,1};
        const float sgX[15] = {1.f,1.f,1.f, 1.f,0.f,-1.f,1.f,0.f,-1.f,
                               1.f,1.f,-1.f,0.f,0.f,1.f};
        const float* S[3] = {wyx0, wyx1, wyx2};
        const float* src = S[loX[pk]];
        if (axF[pk]) {                    // A=x: same linear index, sign-scaled
            val = sgX[pk] * src[(kX[pk] * 32 + w) * 8 + o];
        } else {                          // A=y: transpose c,d
            int d = w / 8, c = w % 8;
            val = src[(kX[pk] * 32 + c * 4 + d) * 8 + o];
        }
    } else {                              // xx fused, CA=CB=4
        int u = t - 9472;
        int o = u / 176, v = u % 176;
        int pk = v / 16, w = v % 16, d = w / 4, c = w % 4;
        const float* S[3] = {wxx0, wxx1, wxx2};
        const float* src = S[loF[pk]];
        val = src[(kaF[pk] * 16 + c * 4 + d) * 8 + o];
        if (kbF[pk] >= 0)
            val += sgF[pk] * src[(kbF[pk] * 16 + d * 4 + c) * 8 + o];
    }
    g_wt[t] = val;
}

// ---------------------------------------------------------------------------
// Kernel 3: edge gather / outer-product / scatter-add (vector atomics)
// ---------------------------------------------------------------------------
__device__ __forceinline__ void red4(float* p, float a, float b, float c, float d) {
    asm volatile("red.global.add.v4.f32 [%0], {%1,%2,%3,%4};"
                 :: "l"(p), "f"(a), "f"(b), "f"(c), "f"(d) : "memory");
}

__global__ void edge_kernel(const float* __restrict__ x0,
                            const float* __restrict__ x1,
                            const float* __restrict__ x2,
                            const float* __restrict__ ev,
                            const int* __restrict__ eidx) {
    int e = blockIdx.x * blockDim.x + threadIdx.x;
    if (e >= N_EDGES) return;
    int src = eidx[e];
    int dst = eidx[N_EDGES + e];
    float2 ee = *(const float2*)(ev + 2 * e);
    float* yb = g_ybuf + (size_t)dst * 72;

    {
        float4 a = *(const float4*)(x0 + (size_t)src * 4);
        red4(yb + 0, ee.x * a.x, ee.x * a.y, ee.x * a.z, ee.x * a.w);
        red4(yb + 4, ee.y * a.x, ee.y * a.y, ee.y * a.z, ee.y * a.w);
    }
    {
        float v[12];
        const float4* p = (const float4*)(x1 + (size_t)src * 12);
        ((float4*)v)[0] = p[0];
        ((float4*)v)[1] = p[1];
        ((float4*)v)[2] = p[2];
#pragma unroll
        for (int m = 0; m < 3; m++) {
            red4(yb + 8 + m * 8,
                 ee.x * v[0 * 3 + m], ee.x * v[1 * 3 + m],
                 ee.x * v[2 * 3 + m], ee.x * v[3 * 3 + m]);
            red4(yb + 8 + m * 8 + 4,
                 ee.y * v[0 * 3 + m], ee.y * v[1 * 3 + m],
                 ee.y * v[2 * 3 + m], ee.y * v[3 * 3 + m]);
        }
    }
    {
        float v[20];
        const float4* p = (const float4*)(x2 + (size_t)src * 20);
        ((float4*)v)[0] = p[0];
        ((float4*)v)[1] = p[1];
        ((float4*)v)[2] = p[2];
        ((float4*)v)[3] = p[3];
        ((float4*)v)[4] = p[4];
#pragma unroll
        for (int m = 0; m < 5; m++) {
            red4(yb + 32 + m * 8,
                 ee.x * v[0 * 5 + m], ee.x * v[1 * 5 + m],
                 ee.x * v[2 * 5 + m], ee.x * v[3 * 5 + m]);
            red4(yb + 32 + m * 8 + 4,
                 ee.y * v[0 * 5 + m], ee.y * v[1 * 5 + m],
                 ee.y * v[2 * 5 + m], ee.y * v[3 * 5 + m]);
        }
    }
}

// ---------------------------------------------------------------------------
// Node-kernel path machinery. H stage as before; P/CG stage uses compile-time
// CG immediates with structural-zero skipping.
// ---------------------------------------------------------------------------

template <int L1, int L2, int LO, int CA, int PP, int QQ>
__device__ __forceinline__ void tail_q(float* __restrict__ acc,
                                       const float (&Ac)[CA],
                                       const float (&H)[CA][2 * L2 + 1]) {
    if constexpr (QQ <= 2 * L2) {
        using C = CGV<L1, L2, LO, PP, QQ>;
        if constexpr (C::v != 0.0f) {
            float Pq = 0.f;
#pragma unroll
            for (int c = 0; c < CA; c++) Pq = fmaf(Ac[c], H[c][QQ], Pq);
            acc[C::MI] = fmaf(C::v, Pq, acc[C::MI]);
        }
        tail_q<L1, L2, LO, CA, PP, QQ + 1>(acc, Ac, H);
    }
}

template <int L1, int L2, int LO, int CA, int PP, typename GA>
__device__ __forceinline__ void tail_p(float* __restrict__ acc,
                                       GA getA,
                                       const float (&H)[CA][2 * L2 + 1]) {
    if constexpr (PP <= 2 * L1) {
        float Ac[CA];
#pragma unroll
        for (int c = 0; c < CA; c++) Ac[c] = getA(c, PP);
        tail_q<L1, L2, LO, CA, PP, 0>(acc, Ac, H);
        tail_p<L1, L2, LO, CA, PP + 1, GA>(acc, getA, H);
    }
}

// yy: A, B register arrays (8ch, [c*(2l+1)+i])
template <int L1, int L2, int LO>
__device__ __forceinline__ void path_rr(float* __restrict__ acc,
                                        const float (&A)[8 * (2 * L1 + 1)],
                                        const float (&B)[8 * (2 * L2 + 1)],
                                        const float* __restrict__ Wt) {
    constexpr int P = 2 * L1 + 1, Q = 2 * L2 + 1;
    float H[8][Q];
#pragma unroll
    for (int c = 0; c < 8; c++)
#pragma unroll
        for (int q = 0; q < Q; q++) H[c][q] = 0.f;
#pragma unroll
    for (int d = 0; d < 8; d++) {
        float Wc[8];
        ((float4*)Wc)[0] = ((const float4*)(Wt + d * 8))[0];
        ((float4*)Wc)[1] = ((const float4*)(Wt + d * 8))[1];
#pragma unroll
        for (int c = 0; c < 8; c++)
#pragma unroll
            for (int q = 0; q < Q; q++) H[c][q] = fmaf(Wc[c], B[d * Q + q], H[c][q]);
    }
    tail_p<L1, L2, LO, 8, 0>(acc, [&](int c, int p) { return A[c * P + p]; }, H);
}

// A = y regs (8ch), B = y smem ([q*8+d], 8ch)
template <int L1, int L2, int LO>
__device__ __forceinline__ void path_ry(float* __restrict__ acc,
                                        const float (&A)[8 * (2 * L1 + 1)],
                                        const float* __restrict__ sBy,
                                        const float* __restrict__ Wt) {
    constexpr int P = 2 * L1 + 1, Q = 2 * L2 + 1;
    float H[8][Q];
#pragma unroll
    for (int c = 0; c < 8; c++)
#pragma unroll
        for (int q = 0; q < Q; q++) H[c][q] = 0.f;
#pragma unroll
    for (int d = 0; d < 8; d++) {
        float Bq[Q];
#pragma unroll
        for (int q = 0; q < Q; q++) Bq[q] = sBy[q * 8 + d];
        float Wc[8];
        ((float4*)Wc)[0] = ((const float4*)(Wt + d * 8))[0];
        ((float4*)Wc)[1] = ((const float4*)(Wt + d * 8))[1];
#pragma unroll
        for (int c = 0; c < 8; c++)
#pragma unroll
            for (int q = 0; q < Q; q++) H[c][q] = fmaf(Wc[c], Bq[q], H[c][q]);
    }
    tail_p<L1, L2, LO, 8, 0>(acc, [&](int c, int p) { return A[c * P + p]; }, H);
}

// A = y smem ([p*8+c]), B = y smem ([q*8+d]), both 8ch
template <int L1, int L2, int LO>
__device__ __forceinline__ void path_yyss(float* __restrict__ acc,
                                          const float* __restrict__ sAy,
                                          const float* __restrict__ sBy,
                                          const float* __restrict__ Wt) {
    constexpr int Q = 2 * L2 + 1;
    float H[8][Q];
#pragma unroll
    for (int c = 0; c < 8; c++)
#pragma unroll
        for (int q = 0; q < Q; q++) H[c][q] = 0.f;
#pragma unroll
    for (int d = 0; d < 8; d++) {
        float Bq[Q];
#pragma unroll
        for (int q = 0; q < Q; q++) Bq[q] = sBy[q * 8 + d];
        float Wc[8];
        ((float4*)Wc)[0] = ((const float4*)(Wt + d * 8))[0];
        ((float4*)Wc)[1] = ((const float4*)(Wt + d * 8))[1];
#pragma unroll
        for (int c = 0; c < 8; c++)
#pragma unroll
            for (int q = 0; q < Q; q++) H[c][q] = fmaf(Wc[c], Bq[q], H[c][q]);
    }
    tail_p<L1, L2, LO, 8, 0>(acc, [&](int c, int p) { return sAy[p * 8 + c]; }, H);
}

// A = y registers (8ch), B = x smem ([d*Q+q], 4ch)
template <int L1, int L2, int LO>
__device__ __forceinline__ void path_rs(float* __restrict__ acc,
                                        const float (&A)[8 * (2 * L1 + 1)],
                                        const float* __restrict__ sB,
                                        const float* __restrict__ Wt) {
    constexpr int P = 2 * L1 + 1, Q = 2 * L2 + 1;
    float H[8][Q];
#pragma unroll
    for (int c = 0; c < 8; c++)
#pragma unroll
        for (int q = 0; q < Q; q++) H[c][q] = 0.f;
#pragma unroll
    for (int d = 0; d < 4; d++) {
        float Bq[Q];
#pragma unroll
        for (int q = 0; q < Q; q++) Bq[q] = sB[d * Q + q];
        float Wc[8];
        ((float4*)Wc)[0] = ((const float4*)(Wt + d * 8))[0];
        ((float4*)Wc)[1] = ((const float4*)(Wt + d * 8))[1];
#pragma unroll
        for (int c = 0; c < 8; c++)
#pragma unroll
            for (int q = 0; q < Q; q++) H[c][q] = fmaf(Wc[c], Bq[q], H[c][q]);
    }
    tail_p<L1, L2, LO, 8, 0>(acc, [&](int c, int p) { return A[c * P + p]; }, H);
}

// A = x registers (4ch), B = y smem ([q*8+d], 8ch)
template <int L1, int L2, int LO>
__device__ __forceinline__ void path_xr(float* __restrict__ acc,
                                        const float (&A)[4 * (2 * L1 + 1)],
                                        const float* __restrict__ sBy,
                                        const float* __restrict__ Wt) {
    constexpr int P = 2 * L1 + 1, Q = 2 * L2 + 1;
    float H[4][Q];
#pragma unroll
    for (int c = 0; c < 4; c++)
#pragma unroll
        for (int q = 0; q < Q; q++) H[c][q] = 0.f;
#pragma unroll
    for (int d = 0; d < 8; d++) {
        float Bq[Q];
#pragma unroll
        for (int q = 0; q < Q; q++) Bq[q] = sBy[q * 8 + d];
        float Wc[4];
        ((float4*)Wc)[0] = ((const float4*)(Wt + d * 4))[0];
#pragma unroll
        for (int c = 0; c < 4; c++)
#pragma unroll
            for (int q = 0; q < Q; q++) H[c][q] = fmaf(Wc[c], Bq[q], H[c][q]);
    }
    tail_p<L1, L2, LO, 4, 0>(acc, [&](int c, int p) { return A[c * P + p]; }, H);
}

// A = y smem ([p*8+c], 8ch), B = x smem ([d*Q+q], 4ch)
template <int L1, int L2, int LO>
__device__ __forceinline__ void path_ys(float* __restrict__ acc,
                                        const float* __restrict__ sAy,
                                        const float* __restrict__ sBx,
                                        const float* __restrict__ Wt) {
    constexpr int Q = 2 * L2 + 1;
    float H[8][Q];
#pragma unroll
    for (int c = 0; c < 8; c++)
#pragma unroll
        for (int q = 0; q < Q; q++) H[c][q] = 0.f;
#pragma unroll
    for (int d = 0; d < 4; d++) {
        float Bq[Q];
#pragma unroll
        for (int q = 0; q < Q; q++) Bq[q] = sBx[d * Q + q];
        float Wc[8];
        ((float4*)Wc)[0] = ((const float4*)(Wt + d * 8))[0];
        ((float4*)Wc)[1] = ((const float4*)(Wt + d * 8))[1];
#pragma unroll
        for (int c = 0; c < 8; c++)
#pragma unroll
            for (int q = 0; q < Q; q++) H[c][q] = fmaf(Wc[c], Bq[q], H[c][q]);
    }
    tail_p<L1, L2, LO, 8, 0>(acc, [&](int c, int p) { return sAy[p * 8 + c]; }, H);
}

// A = x registers (4ch), B = x smem ([d*Q+q], 4ch)
template <int L1, int L2, int LO>
__device__ __forceinline__ void path_xx(float* __restrict__ acc,
                                        const float (&A)[4 * (2 * L1 + 1)],
                                        const float* __restrict__ sBx,
                                        const float* __restrict__ Wt) {
    constexpr int P = 2 * L1 + 1, Q = 2 * L2 + 1;
    float H[4][Q];
#pragma unroll
    for (int c = 0; c < 4; c++)
#pragma unroll
        for (int q = 0; q < Q; q++) H[c][q] = 0.f;
#pragma unroll
    for (int d = 0; d < 4; d++) {
        float Bq[Q];
#pragma unroll
        for (int q = 0; q < Q; q++) Bq[q] = sBx[d * Q + q];
        float Wc[4];
        ((float4*)Wc)[0] = ((const float4*)(Wt + d * 4))[0];
#pragma unroll
        for (int c = 0; c < 4; c++)
#pragma unroll
            for (int q = 0; q < Q; q++) H[c][q] = fmaf(Wc[c], Bq[q], H[c][q]);
    }
    tail_p<L1, L2, LO, 4, 0>(acc, [&](int c, int p) { return A[c * P + p]; }, H);
}

#define SY_STRIDE 73
#define SX_STRIDE 37
#define NPB 8   // nodes per block

__global__ __launch_bounds__(128, 4)
void node_kernel(const float* __restrict__ x0, const float* __restrict__ x1,
                 const float* __restrict__ x2, float* __restrict__ out) {
    __shared__ float s_y[NPB * SY_STRIDE];
    __shared__ float s_x[NPB * SX_STRIDE];
    __shared__ float s_acc[NPB * 8 * 9];   // [(o*NPB+nl)*9 + k]

    int tid = threadIdx.x;
    int nblk = blockIdx.x * NPB;

    for (int i = tid; i < NPB * 72; i += 128) {
        int nl = i / 72, j = i % 72;
        s_y[nl * SY_STRIDE + j] = g_ybuf[(size_t)(nblk + nl) * 72 + j];
    }
    for (int i = tid; i < NPB * 36; i += 128) {
        int nl = i / 36, j = i % 36;
        int gn = nblk + nl;
        float v;
        if (j < 4)       v = x0[(size_t)gn * 4 + j];
        else if (j < 16) v = x1[(size_t)gn * 12 + (j - 4)];
        else             v = x2[(size_t)gn * 20 + (j - 16)];
        s_x[nl * SX_STRIDE + j] = v;
    }
    __syncthreads();

    int half = tid >> 6;
    int ht = tid & 63;
    int nl = ht & 7;
    int o = ht >> 3;
    int n = nblk + nl;

    const float* sy = s_y + nl * SY_STRIDE;
    const float* sx = s_x + nl * SX_STRIDE;

    float acc0[1] = {0.f};
    float acc1[3] = {0.f, 0.f, 0.f};
    float acc2[5] = {0.f, 0.f, 0.f, 0.f, 0.f};

    if (half == 0) {
        // Y1, Y2 in registers; Y0 stays in smem (reg-pressure trim for occ=4)
        float Y1[24], Y2[40];
#pragma unroll
        for (int c = 0; c < 8; c++)
#pragma unroll
            for (int q = 0; q < 3; q++) Y1[c * 3 + q] = sy[8 + q * 8 + c];
#pragma unroll
        for (int c = 0; c < 8; c++)
#pragma unroll
            for (int q = 0; q < 5; q++) Y2[c * 5 + q] = sy[32 + q * 8 + c];

        const float* wyy = g_wt + o * 704;
        path_yyss<0,0,0>(acc0, sy + 0, sy + 0, wyy + 0);
        path_rr<1,1,0>(acc0, Y1, Y1, wyy + 64);
        path_rr<2,2,0>(acc0, Y2, Y2, wyy + 128);
        path_ry<1,0,1>(acc1, Y1, sy + 0, wyy + 192);
        path_rr<1,1,1>(acc1, Y1, Y1, wyy + 256);
        path_rr<2,1,1>(acc1, Y2, Y1, wyy + 320);
        path_rr<2,2,1>(acc1, Y2, Y2, wyy + 384);
        path_ry<2,0,2>(acc2, Y2, sy + 0, wyy + 448);
        path_rr<1,1,2>(acc2, Y1, Y1, wyy + 512);
        path_rr<2,1,2>(acc2, Y2, Y1, wyy + 576);
        path_rr<2,2,2>(acc2, Y2, Y2, wyy + 640);

        const float* wyx = g_wt + 5632 + o * 480;
        path_rs<2,0,2>(acc2, Y2, sx + 0, wyx + 12 * 32);
    } else {
        float X0[4], X1[12], X2[20];
#pragma unroll
        for (int j = 0; j < 4; j++)  X0[j] = sx[j];
#pragma unroll
        for (int j = 0; j < 12; j++) X1[j] = sx[4 + j];
#pragma unroll
        for (int j = 0; j < 20; j++) X2[j] = sx[16 + j];

        const float* wyx = g_wt + 5632 + o * 480;
        path_xr<0,0,0>(acc0, X0, sy + 0,  wyx + 0 * 32);
        path_xr<1,1,0>(acc0, X1, sy + 8,  wyx + 1 * 32);
        path_xr<2,2,0>(acc0, X2, sy + 32, wyx + 2 * 32);
        path_xr<1,0,1>(acc1, X1, sy + 0,  wyx + 3 * 32);
        path_ys<1,0,1>(acc1, sy + 8,  sx + 0,  wyx + 4 * 32);
        path_xr<1,1,1>(acc1, X1, sy + 8,  wyx + 5 * 32);
        path_xr<2,1,1>(acc1, X2, sy + 8,  wyx + 6 * 32);
        path_ys<2,1,1>(acc1, sy + 32, sx + 4,  wyx + 7 * 32);
        path_xr<2,2,1>(acc1, X2, sy + 32, wyx + 8 * 32);
        path_xr<2,0,2>(acc2, X2, sy + 0,  wyx + 9 * 32);
        path_xr<1,1,2>(acc2, X1, sy + 8,  wyx + 10 * 32);
        path_xr<2,1,2>(acc2, X2, sy + 8,  wyx + 11 * 32);
        path_ys<2,1,2>(acc2, sy + 32, sx + 4,  wyx + 13 * 32);
        path_xr<2,2,2>(acc2, X2, sy + 32, wyx + 14 * 32);

        const float* wxx = g_wt + 9472 + o * 176;
        path_xx<0,0,0>(acc0, X0, sx + 0,  wxx + 0);
        path_xx<1,1,0>(acc0, X1, sx + 4,  wxx + 16);
        path_xx<2,2,0>(acc0, X2, sx + 16, wxx + 32);
        path_xx<1,0,1>(acc1, X1, sx + 0,  wxx + 48);
        path_xx<1,1,1>(acc1, X1, sx + 4,  wxx + 64);
        path_xx<2,1,1>(acc1, X2, sx + 4,  wxx + 80);
        path_xx<2,2,1>(acc1, X2, sx + 16, wxx + 96);
        path_xx<2,0,2>(acc2, X2, sx + 0,  wxx + 112);
        path_xx<1,1,2>(acc2, X1, sx + 4,  wxx + 128);
        path_xx<2,1,2>(acc2, X2, sx + 4,  wxx + 144);
        path_xx<2,2,2>(acc2, X2, sx + 16, wxx + 160);
    }

    float* sa = s_acc + (o * NPB + nl) * 9;
    if (half == 1) {
        sa[0] = acc0[0];
        sa[1] = acc1[0]; sa[2] = acc1[1]; sa[3] = acc1[2];
        sa[4] = acc2[0]; sa[5] = acc2[1]; sa[6] = acc2[2];
        sa[7] = acc2[3]; sa[8] = acc2[4];
    }
    __syncthreads();
    if (half == 0) {
        out[n * 8 + o] = acc0[0] + sa[0];
        float* o1 = out + 240000 + ((size_t)n * 8 + o) * 3;
        o1[0] = acc1[0] + sa[1]; o1[1] = acc1[1] + sa[2]; o1[2] = acc1[2] + sa[3];
        float* o2 = out + 960000 + ((size_t)n * 8 + o) * 5;
        o2[0] = acc2[0] + sa[4]; o2[1] = acc2[1] + sa[5]; o2[2] = acc2[2] + sa[6];
        o2[3] = acc2[3] + sa[7]; o2[4] = acc2[4] + sa[8];
    }
}

// ---------------------------------------------------------------------------
extern "C" void kernel_launch(void* const* d_in, const int* in_sizes, int n_in,
                              void* d_out, int out_size) {
    const float* x0   = (const float*)d_in[0];
    const float* x1   = (const float*)d_in[1];
    const float* x2   = (const float*)d_in[2];
    const float* ev   = (const float*)d_in[3];
    const float* Wxx0 = (const float*)d_in[4];
    const float* Wxx1 = (const float*)d_in[5];
    const float* Wxx2 = (const float*)d_in[6];
    const float* Wyx0 = (const float*)d_in[7];
    const float* Wyx1 = (const float*)d_in[8];
    const float* Wyx2 = (const float*)d_in[9];
    const float* Wyy0 = (const float*)d_in[10];
    const float* Wyy1 = (const float*)d_in[11];
    const float* Wyy2 = (const float*)d_in[12];
    const int* eidx   = (const int*)d_in[13];
    float* out = (float*)d_out;

    zero_kernel<<<(N_NODES * 18 + 255) / 256, 256>>>();
    wt_init_kernel<<<(10880 + 255) / 256, 256>>>(Wyy0, Wyy1, Wyy2,
                                                 Wyx0, Wyx1, Wyx2,
                                                 Wxx0, Wxx1, Wxx2);
    edge_kernel<<<(N_EDGES + 255) / 256, 256>>>(x0, x1, x2, ev, eidx);
    node_kernel<<<N_NODES / NPB, 128>>>(x0, x1, x2, out);
}